// round 2
// baseline (speedup 1.0000x reference)
#include <cuda_runtime.h>
#include <cuda_fp16.h>

// Problem constants (fixed shapes from reference)
#define B_   4
#define CIN  256
#define CO_  64
#define N_   576   // H*W = 24*24, both Nk and Nq
#define CV_  256

// Scratch (device globals — no allocation allowed)
__device__ float g_kp[B_ * N_ * CO_];          // (B, Nk, CO)
__device__ float g_qp[B_ * N_ * CO_];          // (B, Nq, CO)
__device__ float g_attn[B_ * N_ * N_];         // (B, Nk, Nq)

// ---------- packed helpers ----------
__device__ __forceinline__ unsigned long long pack2(float lo, float hi) {
    unsigned long long r;
    asm("mov.b64 %0, {%1, %2};" : "=l"(r) : "f"(lo), "f"(hi));
    return r;
}
__device__ __forceinline__ void unpack2(unsigned long long v, float& lo, float& hi) {
    asm("mov.b64 {%0, %1}, %2;" : "=f"(lo), "=f"(hi) : "l"(v));
}
__device__ __forceinline__ unsigned long long ffma2(unsigned long long a,
                                                    unsigned long long b,
                                                    unsigned long long c) {
    unsigned long long d;
    asm("fma.rn.f32x2 %0, %1, %2, %3;" : "=l"(d) : "l"(a), "l"(b), "l"(c));
    return d;
}
__device__ __forceinline__ float tanhfast(float x) {
    float y;
    asm("tanh.approx.f32 %0, %1;" : "=f"(y) : "f"(x));
    return y;
}
__device__ __forceinline__ unsigned tanh_h2(unsigned x) {
    unsigned y;
    asm("tanh.approx.f16x2 %0, %1;" : "=r"(y) : "r"(x));
    return y;
}

// ============================================================================
// Kernel A: 1x1-conv projections.  k_[b,n,c] = sum_ch key[b,ch,n]*Wk[c,ch]+bk[c]
// grid (18 n-tiles of 32, B, 2{k,q}), 256 threads.
// Thread = 1 c x 8 n.  Per ch: 2 LDS.128 (x, warp-broadcast) + 1 LDS.32 (w, CF).
// ============================================================================
__global__ void __launch_bounds__(256) proj_kernel(
    const float* __restrict__ key, const float* __restrict__ query,
    const float* __restrict__ Wk,  const float* __restrict__ bk,
    const float* __restrict__ Wq,  const float* __restrict__ bq)
{
    const int kind = blockIdx.z;
    const float* X    = kind ? query : key;    // (B, CIN, N)
    const float* W    = kind ? Wq    : Wk;     // (CO, CIN)
    const float* bias = kind ? bq    : bk;     // (CO)
    float* outp       = kind ? g_qp  : g_kp;   // (B, N, CO)

    const int b  = blockIdx.y;
    const int n0 = blockIdx.x * 32;

    __shared__ __align__(16) float sX[64][32];   // [ch][n]  rows 128B
    __shared__ __align__(16) float sW[64][65];   // [c][ch]  padded, CF strided reads

    const int t  = threadIdx.x;
    const int c  = t & 63;
    const int ng = t >> 6;          // 0..3 : n = ng*8 .. ng*8+7 (constant per warp!)

    const float bv = bias[c];
    unsigned long long acc[4];
    #pragma unroll
    for (int p = 0; p < 4; p++) acc[p] = pack2(bv, bv);

    for (int ch0 = 0; ch0 < CIN; ch0 += 64) {
        // load X chunk: 64 ch x 32 n (coalesced over n)
        {
            const int n  = t & 31;
            const int cb = t >> 5;
            #pragma unroll
            for (int i = 0; i < 8; i++) {
                const int ch = cb + i * 8;
                sX[ch][n] = X[((size_t)(b * CIN + ch0 + ch)) * N_ + n0 + n];
            }
        }
        // load W chunk: 64 c x 64 ch (coalesced over ch; CF smem stores)
        {
            const int ch = t & 63;
            const int cb = t >> 6;
            #pragma unroll
            for (int i = 0; i < 16; i++) {
                const int cr = cb + i * 4;
                sW[cr][ch] = W[cr * CIN + ch0 + ch];
            }
        }
        __syncthreads();

        #pragma unroll 8
        for (int ch = 0; ch < 64; ch++) {
            const float w = sW[c][ch];
            const unsigned long long ww = pack2(w, w);
            const float4 xa = *(const float4*)&sX[ch][ng * 8];
            const float4 xb = *(const float4*)&sX[ch][ng * 8 + 4];
            acc[0] = ffma2(pack2(xa.x, xa.y), ww, acc[0]);
            acc[1] = ffma2(pack2(xa.z, xa.w), ww, acc[1]);
            acc[2] = ffma2(pack2(xb.x, xb.y), ww, acc[2]);
            acc[3] = ffma2(pack2(xb.z, xb.w), ww, acc[3]);
        }
        __syncthreads();
    }

    // store: out[(b*N + n)*CO + c], lanes write consecutive c -> coalesced
    #pragma unroll
    for (int p = 0; p < 4; p++) {
        float lo, hi;
        unpack2(acc[p], lo, hi);
        const int n = n0 + ng * 8 + 2 * p;
        outp[((size_t)b * N_ + n) * CO_ + c]     = lo;
        outp[((size_t)b * N_ + n + 1) * CO_ + c] = hi;
    }
}

// ============================================================================
// Kernel B: attn[b,k,q] = sigmoid( bf + sum_c tanh(kp[b,k,c]+qp[b,q,c])*wf[c] )
// grid (18 q-tiles, 18 k-tiles, B), 256 threads.
// Thread = 1 k (k = lane) x 4 q (q-group per warp). tanh via f16x2 MUFU
// (halves the MUFU wall); add + accumulate stay fp32.
// ============================================================================
__global__ void __launch_bounds__(256) attn_kernel(
    const float* __restrict__ wf, const float* __restrict__ bfp)
{
    const int b  = blockIdx.z;
    const int k0 = blockIdx.y * 32;
    const int q0 = blockIdx.x * 32;

    __shared__ __align__(16) float sk[32][66];   // row 264B: LDS.64 aligned, CF over k
    __shared__ __align__(16) float sq[32][66];
    __shared__ __align__(16) float swf[64];

    const int t = threadIdx.x;
    {
        const int c  = t & 63;
        const int rb = t >> 6;
        #pragma unroll
        for (int i = 0; i < 8; i++) {
            const int r = rb + i * 4;
            sk[r][c] = g_kp[((size_t)b * N_ + k0 + r) * CO_ + c];
            sq[r][c] = g_qp[((size_t)b * N_ + q0 + r) * CO_ + c];
        }
    }
    if (t < 64) swf[t] = wf[t];
    __syncthreads();

    const int k  = t & 31;          // lane -> conflict-free sk loads
    const int q4 = (t >> 5) * 4;    // 4 q's, constant per warp -> broadcast sq loads

    const float* __restrict__ skr = sk[k];
    const float* __restrict__ s0  = sq[q4 + 0];
    const float* __restrict__ s1  = sq[q4 + 1];
    const float* __restrict__ s2  = sq[q4 + 2];
    const float* __restrict__ s3  = sq[q4 + 3];

    const float bf = bfp[0];
    float a0 = bf, a1 = bf, a2 = bf, a3 = bf;

    #pragma unroll 8
    for (int c = 0; c < 64; c += 2) {
        const float2 kv = *(const float2*)&skr[c];
        const float2 w  = *(const float2*)&swf[c];

        {
            const float2 qv = *(const float2*)&s0[c];
            __half2 h = __floats2half2_rn(kv.x + qv.x, kv.y + qv.y);
            unsigned hu = tanh_h2(*(unsigned*)&h);
            float2 tv = __half22float2(*(__half2*)&hu);
            a0 = fmaf(tv.x, w.x, fmaf(tv.y, w.y, a0));
        }
        {
            const float2 qv = *(const float2*)&s1[c];
            __half2 h = __floats2half2_rn(kv.x + qv.x, kv.y + qv.y);
            unsigned hu = tanh_h2(*(unsigned*)&h);
            float2 tv = __half22float2(*(__half2*)&hu);
            a1 = fmaf(tv.x, w.x, fmaf(tv.y, w.y, a1));
        }
        {
            const float2 qv = *(const float2*)&s2[c];
            __half2 h = __floats2half2_rn(kv.x + qv.x, kv.y + qv.y);
            unsigned hu = tanh_h2(*(unsigned*)&h);
            float2 tv = __half22float2(*(__half2*)&hu);
            a2 = fmaf(tv.x, w.x, fmaf(tv.y, w.y, a2));
        }
        {
            const float2 qv = *(const float2*)&s3[c];
            __half2 h = __floats2half2_rn(kv.x + qv.x, kv.y + qv.y);
            unsigned hu = tanh_h2(*(unsigned*)&h);
            float2 tv = __half22float2(*(__half2*)&hu);
            a3 = fmaf(tv.x, w.x, fmaf(tv.y, w.y, a3));
        }
    }

    // sigmoid(x) = 0.5*tanh(0.5x)+0.5  (fp32 MUFU, 4 per thread: negligible)
    float4 r4;
    r4.x = fmaf(0.5f, tanhfast(0.5f * a0), 0.5f);
    r4.y = fmaf(0.5f, tanhfast(0.5f * a1), 0.5f);
    r4.z = fmaf(0.5f, tanhfast(0.5f * a2), 0.5f);
    r4.w = fmaf(0.5f, tanhfast(0.5f * a3), 0.5f);

    *(float4*)&g_attn[((size_t)b * N_ + k0 + k) * N_ + q0 + q4] = r4;
}

// ============================================================================
// Kernel C: out[b,c,q] = sum_k value[b,c,k] * attn[b,k,q]
// grid (9 q-tiles of 64, 4 c-tiles of 64, B), 256 threads; thread = 4c x 4q.
// V transposed in smem -> both operands via 16B LDS; FFMA2 accumulate.
// ============================================================================
__global__ void __launch_bounds__(256) out_kernel(
    const float* __restrict__ value, float* __restrict__ out)
{
    const int b  = blockIdx.z;
    const int c0 = blockIdx.y * 64;
    const int q0 = blockIdx.x * 64;

    __shared__ __align__(16) float sV[32][68];   // [k][c], row 272B (16B-mult)
    __shared__ __align__(16) float sA[32][64];   // [k][q], row 256B

    const int t  = threadIdx.x;
    const int qg = t & 15;          // q = qg*4 .. +3
    const int cg = t >> 4;          // c = cg*4 .. +3

    unsigned long long acc[4][2];
    #pragma unroll
    for (int i = 0; i < 4; i++) { acc[i][0] = 0ull; acc[i][1] = 0ull; }

    for (int k0 = 0; k0 < N_; k0 += 32) {
        // load V tile 64c x 32k (coalesced over k), transpose into sV[k][c]
        {
            const int kk = t & 31;
            const int cb = t >> 5;
            #pragma unroll
            for (int i = 0; i < 8; i++) {
                const int cr = cb + i * 8;
                sV[kk][cr] = value[((size_t)(b * CV_ + c0 + cr)) * N_ + k0 + kk];
            }
        }
        // load A tile 32k x 64q (coalesced over q, CF smem stores)
        {
            const int q  = t & 63;
            const int kb = t >> 6;
            #pragma unroll
            for (int i = 0; i < 8; i++) {
                const int kr = kb + i * 4;
                sA[kr][q] = g_attn[((size_t)b * N_ + k0 + kr) * N_ + q0 + q];
            }
        }
        __syncthreads();

        #pragma unroll 8
        for (int kk = 0; kk < 32; kk++) {
            const ulonglong2 a2 = *(const ulonglong2*)&sA[kk][qg * 4];   // 4 q
            const float4     v4 = *(const float4*)&sV[kk][cg * 4];      // 4 c
            acc[0][0] = ffma2(pack2(v4.x, v4.x), a2.x, acc[0][0]);
            acc[0][1] = ffma2(pack2(v4.x, v4.x), a2.y, acc[0][1]);
            acc[1][0] = ffma2(pack2(v4.y, v4.y), a2.x, acc[1][0]);
            acc[1][1] = ffma2(pack2(v4.y, v4.y), a2.y, acc[1][1]);
            acc[2][0] = ffma2(pack2(v4.z, v4.z), a2.x, acc[2][0]);
            acc[2][1] = ffma2(pack2(v4.z, v4.z), a2.y, acc[2][1]);
            acc[3][0] = ffma2(pack2(v4.w, v4.w), a2.x, acc[3][0]);
            acc[3][1] = ffma2(pack2(v4.w, v4.w), a2.y, acc[3][1]);
        }
        __syncthreads();
    }

    #pragma unroll
    for (int i = 0; i < 4; i++) {
        float o0, o1, o2, o3;
        unpack2(acc[i][0], o0, o1);
        unpack2(acc[i][1], o2, o3);
        *(float4*)&out[((size_t)(b * CV_ + c0 + cg * 4 + i)) * N_ + q0 + qg * 4] =
            make_float4(o0, o1, o2, o3);
    }
}

// ============================================================================
extern "C" void kernel_launch(void* const* d_in, const int* in_sizes, int n_in,
                              void* d_out, int out_size)
{
    const float* key   = (const float*)d_in[0];
    const float* query = (const float*)d_in[1];
    const float* value = (const float*)d_in[2];
    const float* Wk    = (const float*)d_in[3];
    const float* bk    = (const float*)d_in[4];
    const float* Wq    = (const float*)d_in[5];
    const float* bq    = (const float*)d_in[6];
    const float* wf    = (const float*)d_in[7];
    const float* bf    = (const float*)d_in[8];
    float* out = (float*)d_out;

    proj_kernel<<<dim3(N_ / 32, B_, 2), 256>>>(key, query, Wk, bk, Wq, bq);
    attn_kernel<<<dim3(N_ / 32, N_ / 32, B_), 256>>>(wf, bf);
    out_kernel<<<dim3(N_ / 64, CV_ / 64, B_), 256>>>(value, out);
}